// round 6
// baseline (speedup 1.0000x reference)
#include <cuda_runtime.h>
#include <cstdint>

// ImageWarpingLayer: out = bilinear_sample(image, grid + flow)
// image: [B=16, H=512, W=512, C=8] f32   flow: [B, H, W, 2] f32 (dy, dx)
// TF dense_image_warp semantics: floor clamped to [0, size-2],
// alpha = clip(q - floor, 0, 1).
//
// Work-unit = (pixel, float4-half-of-C): 2 threads/pixel, LDG.128 gathers
// (best measured layout). All addressing in 32-bit byte offsets (image is
// 128MB, fits 2^27). Flow read with .cs (streaming). Output staged in SMEM,
// one 16KB cp.async.bulk (TMA) per 512-thread block.

#define Bn 16
#define Hn 512
#define Wn 512
#define Cn 8

#define THREADS_PER_BLOCK 512
#define UNITS_PER_BLOCK 1024                 // 2 units per thread
#define TOTAL_UNITS (Bn * Hn * Wn * 2)       // 8388608

#define ROW_BYTES (Wn * Cn * 4)              // 16384 bytes per image row
#define PIX_BYTES (Cn * 4)                   // 32 bytes per pixel

__device__ __forceinline__ uint32_t smem_u32(const void* p) {
    uint32_t a;
    asm("{ .reg .u64 t; cvta.to.shared.u64 t, %1; cvt.u32.u64 %0, t; }"
        : "=r"(a) : "l"(p));
    return a;
}

__global__ __launch_bounds__(THREADS_PER_BLOCK)
void warp_kernel(const char* __restrict__ image,
                 const float* __restrict__ flow,
                 float* __restrict__ out)
{
    __shared__ __align__(16) float4 buf[UNITS_PER_BLOCK];  // 16 KB

    const int base = blockIdx.x * UNITS_PER_BLOCK;
    const int t    = threadIdx.x;

#pragma unroll
    for (int k = 0; k < 2; k++) {
        const int slot = t + k * THREADS_PER_BLOCK;
        const int uid  = base + slot;

        const int pix  = uid >> 1;          // pixel id ((b*H + y)*W + x)
        const int half = uid & 1;           // which float4 half of C

        const int x = pix & (Wn - 1);
        const int y = (pix >> 9) & (Hn - 1);
        const int b = pix >> 18;

        // streaming flow load (never reused; keep L1 for image lines)
        const float2 f = __ldcs(reinterpret_cast<const float2*>(flow) + pix);
        const float qy = (float)y + f.x;
        const float qx = (float)x + f.y;

        const float fy = fminf(fmaxf(floorf(qy), 0.0f), (float)(Hn - 2));
        const float fx = fminf(fmaxf(floorf(qx), 0.0f), (float)(Wn - 2));
        const float ay = fminf(fmaxf(qy - fy, 0.0f), 1.0f);
        const float ax = fminf(fmaxf(qx - fx, 0.0f), 1.0f);

        const int iy = (int)fy;
        const int ix = (int)fx;

        // 32-bit byte offset: max (16*512*512*8*4) = 2^27 < 2^31
        const uint32_t top = (uint32_t)(b * Hn + iy) * ROW_BYTES
                           + (uint32_t)ix * PIX_BYTES + (uint32_t)half * 16u;
        const uint32_t bot = top + ROW_BYTES;

        const float4 tl = __ldg(reinterpret_cast<const float4*>(image + top));
        const float4 tr = __ldg(reinterpret_cast<const float4*>(image + top + PIX_BYTES));
        const float4 bl = __ldg(reinterpret_cast<const float4*>(image + bot));
        const float4 br = __ldg(reinterpret_cast<const float4*>(image + bot + PIX_BYTES));

        float4 o;
        float tt, bo;
        tt  = fmaf(ax, tr.x - tl.x, tl.x);
        bo  = fmaf(ax, br.x - bl.x, bl.x);
        o.x = fmaf(ay, bo - tt, tt);
        tt  = fmaf(ax, tr.y - tl.y, tl.y);
        bo  = fmaf(ax, br.y - bl.y, bl.y);
        o.y = fmaf(ay, bo - tt, tt);
        tt  = fmaf(ax, tr.z - tl.z, tl.z);
        bo  = fmaf(ax, br.z - bl.z, bl.z);
        o.z = fmaf(ay, bo - tt, tt);
        tt  = fmaf(ax, tr.w - tl.w, tl.w);
        bo  = fmaf(ax, br.w - bl.w, bl.w);
        o.w = fmaf(ay, bo - tt, tt);

        buf[slot] = o;  // STS.128, conflict-free
    }

    __syncthreads();

    if (t == 0) {
        // Order generic-proxy smem writes before async-proxy read
        asm volatile("fence.proxy.async.shared::cta;" ::: "memory");
        const uint32_t s = smem_u32(buf);
        float* g = out + (long)base * 4;  // 4 floats per unit
        asm volatile(
            "cp.async.bulk.global.shared::cta.bulk_group [%0], [%1], %2;"
            :: "l"(g), "r"(s), "n"(UNITS_PER_BLOCK * 16) : "memory");
        asm volatile("cp.async.bulk.commit_group;" ::: "memory");
        asm volatile("cp.async.bulk.wait_group 0;" ::: "memory");
    }
}

extern "C" void kernel_launch(void* const* d_in, const int* in_sizes, int n_in,
                              void* d_out, int out_size)
{
    const char*  image = (const char*)d_in[0];
    const float* flow  = (const float*)d_in[1];
    float* out = (float*)d_out;

    const int blocks = TOTAL_UNITS / UNITS_PER_BLOCK; // 8192
    warp_kernel<<<blocks, THREADS_PER_BLOCK>>>(image, flow, out);
}

// round 7
// speedup vs baseline: 1.1615x; 1.1615x over previous
#include <cuda_runtime.h>
#include <cstdint>

// ImageWarpingLayer: out = bilinear_sample(image, grid + flow)
// image: [B=16, H=512, W=512, C=8] f32   flow: [B, H, W, 2] f32 (dy, dx)
// TF dense_image_warp semantics: floor clamped to [0, size-2],
// alpha = clip(q - floor, 0, 1).
//
// R4 winning config (256-thread blocks, 2 units/thread, LDG.128 gathers,
// SMEM-staged 8KB TMA bulk store) + 32-bit byte-offset addressing only.

#define Bn 16
#define Hn 512
#define Wn 512
#define Cn 8

#define UNITS_PER_BLOCK 512             // 2 units per thread, 256 threads
#define TOTAL_UNITS (Bn * Hn * Wn * 2)  // 8388608

#define ROW_BYTES (Wn * Cn * 4)         // 16384 bytes per image row
#define PIX_BYTES (Cn * 4)              // 32 bytes per pixel

__device__ __forceinline__ uint32_t smem_u32(const void* p) {
    uint32_t a;
    asm("{ .reg .u64 t; cvta.to.shared.u64 t, %1; cvt.u32.u64 %0, t; }"
        : "=r"(a) : "l"(p));
    return a;
}

__global__ __launch_bounds__(256, 8)
void warp_kernel(const char* __restrict__ image,
                 const float* __restrict__ flow,
                 float* __restrict__ out)
{
    __shared__ __align__(16) float4 buf[UNITS_PER_BLOCK];  // 8 KB

    const int base = blockIdx.x * UNITS_PER_BLOCK;
    const int t    = threadIdx.x;

#pragma unroll
    for (int k = 0; k < 2; k++) {
        const int slot = t + k * 256;
        const int uid  = base + slot;

        const int pix  = uid >> 1;      // pixel id ((b*H + y)*W + x)
        const int half = uid & 1;       // which float4 half of C

        const int x = pix & (Wn - 1);
        const int y = (pix >> 9) & (Hn - 1);
        const int b = pix >> 18;

        const float2 f = __ldg(reinterpret_cast<const float2*>(flow) + pix);
        const float qy = (float)y + f.x;
        const float qx = (float)x + f.y;

        const float fy = fminf(fmaxf(floorf(qy), 0.0f), (float)(Hn - 2));
        const float fx = fminf(fmaxf(floorf(qx), 0.0f), (float)(Wn - 2));
        const float ay = fminf(fmaxf(qy - fy, 0.0f), 1.0f);
        const float ax = fminf(fmaxf(qx - fx, 0.0f), 1.0f);

        const int iy = (int)fy;
        const int ix = (int)fx;

        // 32-bit byte offsets: image is 2^27 bytes, fits easily.
        const uint32_t top = (uint32_t)(b * Hn + iy) * ROW_BYTES
                           + (uint32_t)ix * PIX_BYTES + (uint32_t)(half << 4);
        const uint32_t bot = top + ROW_BYTES;

        const float4 tl = __ldg(reinterpret_cast<const float4*>(image + top));
        const float4 tr = __ldg(reinterpret_cast<const float4*>(image + top + PIX_BYTES));
        const float4 bl = __ldg(reinterpret_cast<const float4*>(image + bot));
        const float4 br = __ldg(reinterpret_cast<const float4*>(image + bot + PIX_BYTES));

        float4 o;
        float tt, bo;
        tt  = fmaf(ax, tr.x - tl.x, tl.x);
        bo  = fmaf(ax, br.x - bl.x, bl.x);
        o.x = fmaf(ay, bo - tt, tt);
        tt  = fmaf(ax, tr.y - tl.y, tl.y);
        bo  = fmaf(ax, br.y - bl.y, bl.y);
        o.y = fmaf(ay, bo - tt, tt);
        tt  = fmaf(ax, tr.z - tl.z, tl.z);
        bo  = fmaf(ax, br.z - bl.z, bl.z);
        o.z = fmaf(ay, bo - tt, tt);
        tt  = fmaf(ax, tr.w - tl.w, tl.w);
        bo  = fmaf(ax, br.w - bl.w, bl.w);
        o.w = fmaf(ay, bo - tt, tt);

        buf[slot] = o;  // STS.128, conflict-free
    }

    __syncthreads();

    if (t == 0) {
        // Order generic-proxy smem writes before async-proxy read
        asm volatile("fence.proxy.async.shared::cta;" ::: "memory");
        const uint32_t s = smem_u32(buf);
        float* g = out + (long)base * 4;  // 4 floats per unit
        asm volatile(
            "cp.async.bulk.global.shared::cta.bulk_group [%0], [%1], %2;"
            :: "l"(g), "r"(s), "n"(UNITS_PER_BLOCK * 16) : "memory");
        asm volatile("cp.async.bulk.commit_group;" ::: "memory");
        asm volatile("cp.async.bulk.wait_group 0;" ::: "memory");
    }
}

extern "C" void kernel_launch(void* const* d_in, const int* in_sizes, int n_in,
                              void* d_out, int out_size)
{
    const char*  image = (const char*)d_in[0];
    const float* flow  = (const float*)d_in[1];
    float* out = (float*)d_out;

    const int blocks = TOTAL_UNITS / UNITS_PER_BLOCK; // 16384
    warp_kernel<<<blocks, 256>>>(image, flow, out);
}

// round 8
// speedup vs baseline: 1.1707x; 1.0080x over previous
#include <cuda_runtime.h>
#include <cstdint>

// ImageWarpingLayer: out = bilinear_sample(image, grid + flow)
// image: [B=16, H=512, W=512, C=8] f32   flow: [B, H, W, 2] f32 (dy, dx)
// TF dense_image_warp semantics: floor clamped to [0, size-2],
// alpha = clip(q - floor, 0, 1).
//
// Work-unit = (pixel, float4-half-of-C): 2 threads/pixel, LDG.128 gathers.
// Output staged in SMEM; each 4KB half is TMA-bulk-stored as soon as it is
// ready, overlapping the first TMA with the second half's compute. Tail wait
// uses wait_group.read (smem-read completion only, not global write-back).

#define Bn 16
#define Hn 512
#define Wn 512
#define Cn 8

#define UNITS_PER_BLOCK 512             // 2 units per thread, 256 threads
#define HALF_UNITS_BLK  256
#define TOTAL_UNITS (Bn * Hn * Wn * 2)  // 8388608

#define ROW_BYTES (Wn * Cn * 4)         // 16384 bytes per image row
#define PIX_BYTES (Cn * 4)              // 32 bytes per pixel

__device__ __forceinline__ uint32_t smem_u32(const void* p) {
    uint32_t a;
    asm("{ .reg .u64 t; cvta.to.shared.u64 t, %1; cvt.u32.u64 %0, t; }"
        : "=r"(a) : "l"(p));
    return a;
}

__global__ __launch_bounds__(256, 8)
void warp_kernel(const char* __restrict__ image,
                 const float* __restrict__ flow,
                 float* __restrict__ out)
{
    __shared__ __align__(16) float4 buf[UNITS_PER_BLOCK];  // 8 KB

    const int base = blockIdx.x * UNITS_PER_BLOCK;
    const int t    = threadIdx.x;

    // ---- front-batched flow loads for both halves ----
    float2 f[2];
#pragma unroll
    for (int k = 0; k < 2; k++) {
        const int pix = (base + t + k * HALF_UNITS_BLK) >> 1;
        f[k] = __ldg(reinterpret_cast<const float2*>(flow) + pix);
    }

#pragma unroll
    for (int k = 0; k < 2; k++) {
        const int slot = t + k * HALF_UNITS_BLK;
        const int uid  = base + slot;

        const int pix  = uid >> 1;      // pixel id ((b*H + y)*W + x)
        const int half = uid & 1;       // which float4 half of C

        const int x = pix & (Wn - 1);
        const int y = (pix >> 9) & (Hn - 1);
        const int b = pix >> 18;

        const float qy = (float)y + f[k].x;
        const float qx = (float)x + f[k].y;

        const float fy = fminf(fmaxf(floorf(qy), 0.0f), (float)(Hn - 2));
        const float fx = fminf(fmaxf(floorf(qx), 0.0f), (float)(Wn - 2));
        const float ay = fminf(fmaxf(qy - fy, 0.0f), 1.0f);
        const float ax = fminf(fmaxf(qx - fx, 0.0f), 1.0f);

        const int iy = (int)fy;
        const int ix = (int)fx;

        // 32-bit byte offsets (image spans 2^27 bytes)
        const uint32_t top = (uint32_t)(b * Hn + iy) * ROW_BYTES
                           + (uint32_t)ix * PIX_BYTES + (uint32_t)(half << 4);
        const uint32_t bot = top + ROW_BYTES;

        const float4 tl = __ldg(reinterpret_cast<const float4*>(image + top));
        const float4 tr = __ldg(reinterpret_cast<const float4*>(image + top + PIX_BYTES));
        const float4 bl = __ldg(reinterpret_cast<const float4*>(image + bot));
        const float4 br = __ldg(reinterpret_cast<const float4*>(image + bot + PIX_BYTES));

        float4 o;
        float tt, bo;
        tt  = fmaf(ax, tr.x - tl.x, tl.x);
        bo  = fmaf(ax, br.x - bl.x, bl.x);
        o.x = fmaf(ay, bo - tt, tt);
        tt  = fmaf(ax, tr.y - tl.y, tl.y);
        bo  = fmaf(ax, br.y - bl.y, bl.y);
        o.y = fmaf(ay, bo - tt, tt);
        tt  = fmaf(ax, tr.z - tl.z, tl.z);
        bo  = fmaf(ax, br.z - bl.z, bl.z);
        o.z = fmaf(ay, bo - tt, tt);
        tt  = fmaf(ax, tr.w - tl.w, tl.w);
        bo  = fmaf(ax, br.w - bl.w, bl.w);
        o.w = fmaf(ay, bo - tt, tt);

        buf[slot] = o;  // STS.128, conflict-free

        // After half k is fully staged, kick its 4KB TMA store. The k=0
        // store drains while the block computes k=1.
        __syncthreads();
        if (t == 0) {
            asm volatile("fence.proxy.async.shared::cta;" ::: "memory");
            const uint32_t s = smem_u32(buf) + k * (HALF_UNITS_BLK * 16);
            float* g = out + (long)(base + k * HALF_UNITS_BLK) * 4;
            asm volatile(
                "cp.async.bulk.global.shared::cta.bulk_group [%0], [%1], %2;"
                :: "l"(g), "r"(s), "n"(HALF_UNITS_BLK * 16) : "memory");
            asm volatile("cp.async.bulk.commit_group;" ::: "memory");
        }
    }

    // Only t==0 issued the TMAs; it alone must ensure SMEM has been fully
    // read before the block exits (smem slot reuse by the next block).
    if (t == 0) {
        asm volatile("cp.async.bulk.wait_group.read 0;" ::: "memory");
    }
}

extern "C" void kernel_launch(void* const* d_in, const int* in_sizes, int n_in,
                              void* d_out, int out_size)
{
    const char*  image = (const char*)d_in[0];
    const float* flow  = (const float*)d_in[1];
    float* out = (float*)d_out;

    const int blocks = TOTAL_UNITS / UNITS_PER_BLOCK; // 16384
    warp_kernel<<<blocks, 256>>>(image, flow, out);
}